// round 14
// baseline (speedup 1.0000x reference)
#include <cuda_runtime.h>
#include <cstdint>
#include <cstddef>

#define S_LEN 2048
#define BATCH 512
#define VDIM  29
#define HDIM  128
#define KTOT  160            // 128 (h) + 29 (x) padded to 160 — x inline
#define NWARP 8              // k-split chunks per row-pair
#define KC    (KTOT / NWARP) // 20 k's per chunk
#define ROWS  4              // batch rows per CTA

// intermediate encoder state (static device scratch — no allocation)
__device__ float g_enc[BATCH * HDIM];

typedef unsigned long long ull;

__device__ __forceinline__ ull pack2(float lo, float hi) {
    ull r; asm("mov.b64 %0, {%1, %2};" : "=l"(r) : "f"(lo), "f"(hi)); return r;
}
__device__ __forceinline__ ull fma2(ull a, ull b, ull c) {
    ull d; asm("fma.rn.f32x2 %0, %1, %2, %3;" : "=l"(d) : "l"(a), "l"(b), "l"(c)); return d;
}
__device__ __forceinline__ float fast_tanh(float x) {
    float ax = fabsf(x);
    float t  = __expf(-2.0f * ax);                 // MUFU.EX2 path
    float r  = __fdividef(1.0f - t, 1.0f + t);     // MUFU.RCP path
    return copysignf(r, x);
}

// ---------------------------------------------------------------------------
// Encoder: R12 verbatim (best measured). 128 CTAs x 4 rows x 512 threads.
// Warp w: chunk=w&7 owns k in [chunk*20,+20), rowpair rp=w>>3 owns rows
// (2rp,2rp+1). Weight col-pairs in registers; state duplicated (h0,h0,h1,h1)
// so one LDS.128 per k feeds 4 fma2. Partials stored as raw ulonglong2
// accumulator pairs; 8-way k-partials reduced by all 512 threads; MUFU tanh.
// ---------------------------------------------------------------------------
__global__ void __launch_bounds__(512, 1) enc_kernel(
    const float* __restrict__ x, const float* __restrict__ We_ih,
    const float* __restrict__ We_hh, const float* __restrict__ be_ih,
    const float* __restrict__ be_hh)
{
    extern __shared__ float sm[];
    float* Wt  = sm;                      // [KTOT][HDIM] k-major staging
    float* gb  = Wt + KTOT * HDIM;        // [2 buf][2 rowpair][KTOT][4] dup state
    float* red = gb + 2 * 2 * KTOT * 4;   // [NWARP][4 rows][HDIM] partials

    const int tid  = threadIdx.x;
    const int warp = tid >> 5, lane = tid & 31;
    const int chunk = warp & 7;
    const int rp    = warp >> 3;          // 0: rows 0,1   1: rows 2,3
    const int rowbase = blockIdx.x * ROWS;

    // Build k-major combined weight [We_hh | We_ih | 0-pad], zero state bufs
    for (int i = tid; i < KTOT * HDIM; i += 512) {
        int k = i >> 7, j = i & (HDIM - 1);
        float w = 0.f;
        if (k < HDIM)             w = We_hh[j * HDIM + k];
        else if (k < HDIM + VDIM) w = We_ih[j * VDIM + (k - HDIM)];
        Wt[i] = w;
    }
    for (int i = tid; i < 2 * 2 * KTOT * 4; i += 512) gb[i] = 0.f;   // h=0, pads=0
    __syncthreads();

    const int k0 = chunk * KC;
    ull wlo[KC], whi[KC];                 // pre-packed col pairs (80 regs)
    #pragma unroll
    for (int kk = 0; kk < KC; ++kk) {
        const float4 w4 = *(const float4*)(Wt + (k0 + kk) * HDIM + 4 * lane);
        wlo[kk] = pack2(w4.x, w4.y);
        whi[kk] = pack2(w4.z, w4.w);
    }

    // x_0 into buffer 0's x-region (duplicated pairs)
    if (tid < ROWS * VDIM) {
        int r = tid / VDIM, v = tid - r * VDIM;
        float xv = x[((size_t)(rowbase + r) * S_LEN) * VDIM + v];
        *(float2*)(gb + ((r >> 1) * KTOT + HDIM + v) * 4 + 2 * (r & 1)) =
            make_float2(xv, xv);
    }
    __syncthreads();

    // finalize mapping: 512 threads = 128 j x 4 rows; bias in register
    const int jf = tid & (HDIM - 1);
    const int rr = tid >> 7;              // row 0..3
    const float biasr = be_ih[jf] + be_hh[jf];
    const float* redr = red + rr * HDIM + jf;          // + c*4*HDIM per chunk
    float* gout = g_enc + (rowbase + rr) * HDIM + jf;

    // invariant hot-loop pointers
    ull* rb0 = (ull*)(red + (chunk * 4 + rp * 2) * HDIM + 4 * lane);
    ull* rb1 = (ull*)(red + (chunk * 4 + rp * 2 + 1) * HDIM + 4 * lane);
    const float* gkA = gb + (rp * KTOT + k0) * 4;                    // buf 0
    const float* gkB = gkA + 2 * KTOT * 4;                           // buf 1
    float* gwA = gb + ((rr >> 1) * KTOT + jf) * 4 + 2 * (rr & 1);    // buf 0
    float* gwB = gwA + 2 * KTOT * 4;                                 // buf 1

    for (int t = 0; t < S_LEN; ++t) {
        // prefetch next step's x (latency hidden under the GEMV)
        float xr = 0.f; int xslot = -1;
        if (tid < ROWS * VDIM && t + 1 < S_LEN) {
            int r = tid / VDIM, v = tid - r * VDIM;
            xr = x[((size_t)(rowbase + r) * S_LEN + (t + 1)) * VDIM + v];
            xslot = ((t & 1) ^ 1) * (2 * KTOT * 4)
                  + ((r >> 1) * KTOT + HDIM + v) * 4 + 2 * (r & 1);
        }

        ull aL0 = 0, aH0 = 0, aL1 = 0, aH1 = 0;
        const float* gk = (t & 1) ? gkB : gkA;
        #pragma unroll
        for (int kk = 0; kk < KC; ++kk) {
            const ulonglong2 gg = *(const ulonglong2*)(gk + kk * 4);  // 1 LDS.128
            aL0 = fma2(wlo[kk], gg.x, aL0); aH0 = fma2(whi[kk], gg.x, aH0);
            aL1 = fma2(wlo[kk], gg.y, aL1); aH1 = fma2(whi[kk], gg.y, aH1);
        }
        // partials are already in red's layout: (c0,c1,c2,c3) = {aLx, aHx}
        *(ulonglong2*)rb0 = make_ulonglong2(aL0, aH0);   // row rp*2
        *(ulonglong2*)rb1 = make_ulonglong2(aL1, aH1);   // row rp*2+1
        if (xslot >= 0) *(float2*)(gb + xslot) = make_float2(xr, xr);
        __syncthreads();

        // finalize: 512 threads, each sums 8 partials for (jf, rr), tanh
        {
            float s = biasr;
            #pragma unroll
            for (int c = 0; c < NWARP; ++c)
                s += redr[c * 4 * HDIM];
            float h = fast_tanh(s);
            float* gw = (t & 1) ? gwA : gwB;   // write buffer for t+1
            *(float2*)gw = make_float2(h, h);
            if (t == S_LEN - 1) *gout = h;
        }
        __syncthreads();
    }
}

// ---------------------------------------------------------------------------
// Decoder: TWO batch rows per warp, interleaved — the chain is latency-bound
// (~215 cyc/step at 1 row/warp vs ~60 issue slots), so a second independent
// chain hides the first's LDS/FMA/MUFU stalls. Weights Wp are shared across
// rows (same registers). 64 CTAs x 4 warps x 2 rows = 512 rows.
// h in per-warp double-buffered SMEM (broadcast LDS.128), MUFU tanh.
// ---------------------------------------------------------------------------
__global__ void __launch_bounds__(128) dec_kernel(
    const float* __restrict__ Wd_ih, const float* __restrict__ Wd_hh,
    const float* __restrict__ bd_ih, const float* __restrict__ bd_hh,
    float* __restrict__ out)
{
    __shared__ float hbuf[2][4][2][32];   // [buf][warp][row][lane]
    const int warp = threadIdx.x >> 5, lane = threadIdx.x & 31;
    const int b0 = blockIdx.x * 8 + warp * 2;
    const bool act = lane < VDIM;
    const int vl = act ? lane : 0;

    float Wp[32];                         // padded Wd_hh row, shared by both rows
    #pragma unroll
    for (int u = 0; u < 32; ++u) Wp[u] = (u < VDIM) ? Wd_hh[vl * VDIM + u] : 0.f;

    // one-time dec_in for both rows
    const float bsum = bd_ih[vl] + bd_hh[vl];
    float din[2];
    #pragma unroll
    for (int r = 0; r < 2; ++r) {
        const float* er = g_enc + (size_t)(b0 + r) * HDIM;
        float e0 = er[lane], e1 = er[32 + lane], e2 = er[64 + lane], e3 = er[96 + lane];
        const float* wi = Wd_ih + vl * HDIM;
        float s0 = 0, s1 = 0, s2 = 0, s3 = 0;
        #pragma unroll
        for (int k = 0; k < 32; ++k) {
            s0 += wi[k]      * __shfl_sync(0xffffffffu, e0, k);
            s1 += wi[32 + k] * __shfl_sync(0xffffffffu, e1, k);
            s2 += wi[64 + k] * __shfl_sync(0xffffffffu, e2, k);
            s3 += wi[96 + k] * __shfl_sync(0xffffffffu, e3, k);
        }
        din[r] = bsum + (s0 + s1) + (s2 + s3);
    }

    hbuf[0][warp][0][lane] = 0.f;         // h_0 = 0 for both rows
    hbuf[0][warp][1][lane] = 0.f;
    __syncwarp();

    float* o0 = out + (size_t)b0 * S_LEN * VDIM + lane;
    float* o1 = o0 + (size_t)S_LEN * VDIM;
    for (int s = 0; s < S_LEN; ++s) {
        const float* u = hbuf[s & 1][warp][0];
        const float* v = hbuf[s & 1][warp][1];
        float p0 = din[0], p1 = 0.f, p2 = 0.f, p3 = 0.f;
        float r0 = din[1], r1 = 0.f, r2 = 0.f, r3 = 0.f;
        #pragma unroll
        for (int c = 0; c < 8; ++c) {
            const float4 U = *(const float4*)(u + 4 * c);   // broadcast LDS.128
            const float4 V = *(const float4*)(v + 4 * c);
            p0 = fmaf(Wp[4 * c],     U.x, p0); r0 = fmaf(Wp[4 * c],     V.x, r0);
            p1 = fmaf(Wp[4 * c + 1], U.y, p1); r1 = fmaf(Wp[4 * c + 1], V.y, r1);
            p2 = fmaf(Wp[4 * c + 2], U.z, p2); r2 = fmaf(Wp[4 * c + 2], V.z, r2);
            p3 = fmaf(Wp[4 * c + 3], U.w, p3); r3 = fmaf(Wp[4 * c + 3], V.w, r3);
        }
        float hn0 = fast_tanh((p0 + p1) + (p2 + p3));
        float hn1 = fast_tanh((r0 + r1) + (r2 + r3));
        hbuf[(s & 1) ^ 1][warp][0][lane] = hn0;   // pads multiply by 0 next step
        hbuf[(s & 1) ^ 1][warp][1][lane] = hn1;
        if (act) {
            o0[(size_t)s * VDIM] = hn0;
            o1[(size_t)s * VDIM] = hn1;
        }
        __syncwarp();
    }
}

// ---------------------------------------------------------------------------
extern "C" void kernel_launch(void* const* d_in, const int* in_sizes, int n_in,
                              void* d_out, int out_size) {
    const float* x     = (const float*)d_in[0];
    const float* We_ih = (const float*)d_in[1];
    const float* We_hh = (const float*)d_in[2];
    const float* be_ih = (const float*)d_in[3];
    const float* be_hh = (const float*)d_in[4];
    const float* Wd_ih = (const float*)d_in[5];
    const float* Wd_hh = (const float*)d_in[6];
    const float* bd_ih = (const float*)d_in[7];
    const float* bd_hh = (const float*)d_in[8];
    float* out = (float*)d_out;

    const int smem = (KTOT * HDIM + 2 * 2 * KTOT * 4 + NWARP * 4 * HDIM) * 4; // 108544 B
    cudaFuncSetAttribute(enc_kernel, cudaFuncAttributeMaxDynamicSharedMemorySize, smem);

    enc_kernel<<<BATCH / ROWS, 512, smem>>>(x, We_ih, We_hh, be_ih, be_hh);
    dec_kernel<<<BATCH / 8, 128>>>(Wd_ih, Wd_hh, bd_ih, bd_hh, out);
}

// round 15
// speedup vs baseline: 1.5145x; 1.5145x over previous
#include <cuda_runtime.h>
#include <cstdint>
#include <cstddef>

#define S_LEN 2048
#define BATCH 512
#define VDIM  29
#define HDIM  128
#define KTOT  160            // 128 (h) + 29 (x) padded to 160 — x inline
#define NWARP 8              // k-split chunks per row-pair
#define KC    (KTOT / NWARP) // 20 k's per chunk
#define ROWS  4              // batch rows per CTA

// intermediate encoder state (static device scratch — no allocation)
__device__ float g_enc[BATCH * HDIM];

typedef unsigned long long ull;

__device__ __forceinline__ ull pack2(float lo, float hi) {
    ull r; asm("mov.b64 %0, {%1, %2};" : "=l"(r) : "f"(lo), "f"(hi)); return r;
}
__device__ __forceinline__ ull fma2(ull a, ull b, ull c) {
    ull d; asm("fma.rn.f32x2 %0, %1, %2, %3;" : "=l"(d) : "l"(a), "l"(b), "l"(c)); return d;
}
// tanh(x) = 1 - 2/(1 + e^{2x}) : no fabs/copysign in the chain; saturates
// correctly at both infinities (e^{2x}->0 => -1, ->inf => +1).
__device__ __forceinline__ float fast_tanh(float x) {
    float t = __expf(2.0f * x);                    // FMUL + MUFU.EX2
    return 1.0f - __fdividef(2.0f, 1.0f + t);      // FADD + MUFU.RCP + FMUL + FADD
}

// ---------------------------------------------------------------------------
// Encoder: R12 exact structure (best measured). 128 CTAs x 4 rows x 512 thr.
// Warp w: chunk=w&7 owns k in [chunk*20,+20), rowpair rp=w>>3 owns rows
// (2rp,2rp+1). Weight col-pairs in registers; state duplicated (h0,h0,h1,h1)
// so one LDS.128 per k feeds 4 fma2. Partials stored as raw ulonglong2
// accumulator pairs; 8-way k-partials reduced by all 512 threads.
// Deltas vs R12: balanced-tree partial reduction, cheaper tanh.
// ---------------------------------------------------------------------------
__global__ void __launch_bounds__(512, 1) enc_kernel(
    const float* __restrict__ x, const float* __restrict__ We_ih,
    const float* __restrict__ We_hh, const float* __restrict__ be_ih,
    const float* __restrict__ be_hh)
{
    extern __shared__ float sm[];
    float* Wt  = sm;                      // [KTOT][HDIM] k-major staging
    float* gb  = Wt + KTOT * HDIM;        // [2 buf][2 rowpair][KTOT][4] dup state
    float* red = gb + 2 * 2 * KTOT * 4;   // [NWARP][4 rows][HDIM] partials

    const int tid  = threadIdx.x;
    const int warp = tid >> 5, lane = tid & 31;
    const int chunk = warp & 7;
    const int rp    = warp >> 3;          // 0: rows 0,1   1: rows 2,3
    const int rowbase = blockIdx.x * ROWS;

    // Build k-major combined weight [We_hh | We_ih | 0-pad], zero state bufs
    for (int i = tid; i < KTOT * HDIM; i += 512) {
        int k = i >> 7, j = i & (HDIM - 1);
        float w = 0.f;
        if (k < HDIM)             w = We_hh[j * HDIM + k];
        else if (k < HDIM + VDIM) w = We_ih[j * VDIM + (k - HDIM)];
        Wt[i] = w;
    }
    for (int i = tid; i < 2 * 2 * KTOT * 4; i += 512) gb[i] = 0.f;   // h=0, pads=0
    __syncthreads();

    const int k0 = chunk * KC;
    ull wlo[KC], whi[KC];                 // pre-packed col pairs (80 regs)
    #pragma unroll
    for (int kk = 0; kk < KC; ++kk) {
        const float4 w4 = *(const float4*)(Wt + (k0 + kk) * HDIM + 4 * lane);
        wlo[kk] = pack2(w4.x, w4.y);
        whi[kk] = pack2(w4.z, w4.w);
    }

    // x_0 into buffer 0's x-region (duplicated pairs)
    if (tid < ROWS * VDIM) {
        int r = tid / VDIM, v = tid - r * VDIM;
        float xv = x[((size_t)(rowbase + r) * S_LEN) * VDIM + v];
        *(float2*)(gb + ((r >> 1) * KTOT + HDIM + v) * 4 + 2 * (r & 1)) =
            make_float2(xv, xv);
    }
    __syncthreads();

    // finalize mapping: 512 threads = 128 j x 4 rows; bias in register
    const int jf = tid & (HDIM - 1);
    const int rr = tid >> 7;              // row 0..3
    const float biasr = be_ih[jf] + be_hh[jf];
    const float* redr = red + rr * HDIM + jf;          // + c*4*HDIM per chunk
    float* gout = g_enc + (rowbase + rr) * HDIM + jf;

    // invariant hot-loop pointers
    ull* rb0 = (ull*)(red + (chunk * 4 + rp * 2) * HDIM + 4 * lane);
    ull* rb1 = (ull*)(red + (chunk * 4 + rp * 2 + 1) * HDIM + 4 * lane);
    const float* gkA = gb + (rp * KTOT + k0) * 4;                    // buf 0
    const float* gkB = gkA + 2 * KTOT * 4;                           // buf 1
    float* gwA = gb + ((rr >> 1) * KTOT + jf) * 4 + 2 * (rr & 1);    // buf 0
    float* gwB = gwA + 2 * KTOT * 4;                                 // buf 1

    for (int t = 0; t < S_LEN; ++t) {
        // prefetch next step's x (latency hidden under the GEMV)
        float xr = 0.f; int xslot = -1;
        if (tid < ROWS * VDIM && t + 1 < S_LEN) {
            int r = tid / VDIM, v = tid - r * VDIM;
            xr = x[((size_t)(rowbase + r) * S_LEN + (t + 1)) * VDIM + v];
            xslot = ((t & 1) ^ 1) * (2 * KTOT * 4)
                  + ((r >> 1) * KTOT + HDIM + v) * 4 + 2 * (r & 1);
        }

        ull aL0 = 0, aH0 = 0, aL1 = 0, aH1 = 0;
        const float* gk = (t & 1) ? gkB : gkA;
        #pragma unroll
        for (int kk = 0; kk < KC; ++kk) {
            const ulonglong2 gg = *(const ulonglong2*)(gk + kk * 4);  // 1 LDS.128
            aL0 = fma2(wlo[kk], gg.x, aL0); aH0 = fma2(whi[kk], gg.x, aH0);
            aL1 = fma2(wlo[kk], gg.y, aL1); aH1 = fma2(whi[kk], gg.y, aH1);
        }
        // partials are already in red's layout: (c0,c1,c2,c3) = {aLx, aHx}
        *(ulonglong2*)rb0 = make_ulonglong2(aL0, aH0);   // row rp*2
        *(ulonglong2*)rb1 = make_ulonglong2(aL1, aH1);   // row rp*2+1
        if (xslot >= 0) *(float2*)(gb + xslot) = make_float2(xr, xr);
        __syncthreads();

        // finalize: 512 threads, each sums 8 partials for (jf, rr) as a
        // balanced tree (depth 3+1 vs serial 8), tanh
        {
            const float p0 = redr[0 * 4 * HDIM], p1 = redr[1 * 4 * HDIM];
            const float p2 = redr[2 * 4 * HDIM], p3 = redr[3 * 4 * HDIM];
            const float p4 = redr[4 * 4 * HDIM], p5 = redr[5 * 4 * HDIM];
            const float p6 = redr[6 * 4 * HDIM], p7 = redr[7 * 4 * HDIM];
            float s = (biasr + ((p0 + p1) + (p2 + p3))) + ((p4 + p5) + (p6 + p7));
            float h = fast_tanh(s);
            float* gw = (t & 1) ? gwA : gwB;   // write buffer for t+1
            *(float2*)gw = make_float2(h, h);
            if (t == S_LEN - 1) *gout = h;
        }
        __syncthreads();
    }
}

// ---------------------------------------------------------------------------
// Decoder: R12 exact structure (best measured: 1 row/warp, all 512 rows
// concurrent, wall = chain latency). 128 CTAs x 4 warps. h in per-warp
// double-buffered SMEM (broadcast LDS.128), 4 FMA accumulators, cheap tanh.
// W row padded to 32 with zeros so pad lanes are harmless.
// ---------------------------------------------------------------------------
__global__ void __launch_bounds__(128) dec_kernel(
    const float* __restrict__ Wd_ih, const float* __restrict__ Wd_hh,
    const float* __restrict__ bd_ih, const float* __restrict__ bd_hh,
    float* __restrict__ out)
{
    __shared__ float hbuf[2][4][32];
    const int warp = threadIdx.x >> 5, lane = threadIdx.x & 31;
    const int b = blockIdx.x * 4 + warp;
    const float* er = g_enc + b * HDIM;
    float e0 = er[lane], e1 = er[32 + lane], e2 = er[64 + lane], e3 = er[96 + lane];
    const bool act = lane < VDIM;
    const int vl = act ? lane : 0;

    float Wp[32];
    #pragma unroll
    for (int u = 0; u < 32; ++u) Wp[u] = (u < VDIM) ? Wd_hh[vl * VDIM + u] : 0.f;

    float din = bd_ih[vl] + bd_hh[vl];
    {
        const float* wi = Wd_ih + vl * HDIM;
        float s0 = 0, s1 = 0, s2 = 0, s3 = 0;
        #pragma unroll
        for (int k = 0; k < 32; ++k) {
            s0 += wi[k]      * __shfl_sync(0xffffffffu, e0, k);
            s1 += wi[32 + k] * __shfl_sync(0xffffffffu, e1, k);
            s2 += wi[64 + k] * __shfl_sync(0xffffffffu, e2, k);
            s3 += wi[96 + k] * __shfl_sync(0xffffffffu, e3, k);
        }
        din += (s0 + s1) + (s2 + s3);
    }

    hbuf[0][warp][lane] = 0.f;
    __syncwarp();

    float* orow = out + (size_t)b * S_LEN * VDIM + lane;
    for (int s = 0; s < S_LEN; ++s) {
        const float* hv = hbuf[s & 1][warp];
        float q0 = din, q1 = 0.f, q2 = 0.f, q3 = 0.f;
        #pragma unroll
        for (int c = 0; c < 8; ++c) {
            const float4 hh = *(const float4*)(hv + 4 * c);   // broadcast LDS.128
            q0 = fmaf(Wp[4 * c],     hh.x, q0);
            q1 = fmaf(Wp[4 * c + 1], hh.y, q1);
            q2 = fmaf(Wp[4 * c + 2], hh.z, q2);
            q3 = fmaf(Wp[4 * c + 3], hh.w, q3);
        }
        float hn = fast_tanh((q0 + q1) + (q2 + q3));
        hbuf[(s & 1) ^ 1][warp][lane] = hn;   // pads multiply by 0 next step
        if (act) orow[(size_t)s * VDIM] = hn;
        __syncwarp();
    }
}

// ---------------------------------------------------------------------------
extern "C" void kernel_launch(void* const* d_in, const int* in_sizes, int n_in,
                              void* d_out, int out_size) {
    const float* x     = (const float*)d_in[0];
    const float* We_ih = (const float*)d_in[1];
    const float* We_hh = (const float*)d_in[2];
    const float* be_ih = (const float*)d_in[3];
    const float* be_hh = (const float*)d_in[4];
    const float* Wd_ih = (const float*)d_in[5];
    const float* Wd_hh = (const float*)d_in[6];
    const float* bd_ih = (const float*)d_in[7];
    const float* bd_hh = (const float*)d_in[8];
    float* out = (float*)d_out;

    const int smem = (KTOT * HDIM + 2 * 2 * KTOT * 4 + NWARP * 4 * HDIM) * 4; // 108544 B
    cudaFuncSetAttribute(enc_kernel, cudaFuncAttributeMaxDynamicSharedMemorySize, smem);

    enc_kernel<<<BATCH / ROWS, 512, smem>>>(x, We_ih, We_hh, be_ih, be_hh);
    dec_kernel<<<BATCH / 4, 128>>>(Wd_ih, Wd_hh, bd_ih, bd_hh, out);
}